// round 4
// baseline (speedup 1.0000x reference)
#include <cuda_runtime.h>
#include <cstdint>

#define N_NODES 2048
#define F_DIM   128
#define UNITS   128
#define FE_DIM  16
#define DEG     64

__device__ float g_hr[N_NODES * UNITS];
__device__ float g_al[N_NODES];
__device__ float g_ar[N_NODES];

__device__ __forceinline__ float lrelu(float x) {
    return x > 0.0f ? x : 0.2f * x;
}

// Packed f32x2 helpers (sm_103a; ptxas won't auto-fuse — PTX only)
__device__ __forceinline__ unsigned long long pack2(float lo, float hi) {
    unsigned long long r;
    asm("mov.b64 %0, {%1, %2};" : "=l"(r) : "f"(lo), "f"(hi));
    return r;
}
__device__ __forceinline__ void unpack2(float& lo, float& hi, unsigned long long v) {
    asm("mov.b64 {%0, %1}, %2;" : "=f"(lo), "=f"(hi) : "l"(v));
}
__device__ __forceinline__ void fma2(unsigned long long& d,
                                     unsigned long long a,
                                     unsigned long long b) {
    asm("fma.rn.f32x2 %0, %1, %2, %3;" : "=l"(d) : "l"(a), "l"(b), "l"(d));
}

// Kernel 1: C = ns @ [Wl | Wr]; store hr; reduce al/ar.
// 16 nodes per block, 256 threads: t&127 = output column, t>>7 = side (0=L,1=R).
// Node tile transposed in smem; inner loop = 8 packed FFMA2 per k per thread.
#define NPB   16
#define NSPAD 20   // row stride 80B: 16B-aligned for ulonglong2 reads
__global__ __launch_bounds__(256)
void gemm_kernel(const float* __restrict__ ns,
                 const float* __restrict__ Wl,
                 const float* __restrict__ Wr,
                 const float* __restrict__ W_attn) {
    const int t    = threadIdx.x;
    const int col  = t & 127;
    const int side = t >> 7;
    const int n0   = blockIdx.x * NPB;

    __shared__ float s_ns[F_DIM][NSPAD];   // [k][node]
    #pragma unroll
    for (int i = 0; i < 8; i++) {
        const int lin = t + i * 256;       // 2048 elements
        const int j = lin >> 7, c = lin & 127;
        s_ns[c][j] = ns[(n0 + j) * F_DIM + c];
    }
    __syncthreads();

    const float* __restrict__ W = side ? Wr : Wl;

    unsigned long long acc[8];
    #pragma unroll
    for (int j = 0; j < 8; j++) acc[j] = 0ull;

    #pragma unroll 4
    for (int k = 0; k < F_DIM; k++) {
        const float wv = __ldcg(&W[k * UNITS + col]);   // coalesced 128B/warp
        const unsigned long long wp = pack2(wv, wv);
        const ulonglong2* row = reinterpret_cast<const ulonglong2*>(&s_ns[k][0]);
        const ulonglong2 r0 = row[0];   // nodes (0,1),(2,3)
        const ulonglong2 r1 = row[1];   // (4,5),(6,7)
        const ulonglong2 r2 = row[2];   // (8,9),(10,11)
        const ulonglong2 r3 = row[3];   // (12,13),(14,15)
        fma2(acc[0], r0.x, wp);  fma2(acc[1], r0.y, wp);
        fma2(acc[2], r1.x, wp);  fma2(acc[3], r1.y, wp);
        fma2(acc[4], r2.x, wp);  fma2(acc[5], r2.y, wp);
        fma2(acc[6], r3.x, wp);  fma2(acc[7], r3.y, wp);
    }

    float h[NPB];
    #pragma unroll
    for (int j = 0; j < 8; j++) unpack2(h[2 * j], h[2 * j + 1], acc[j]);

    // side 1 stores hr (coalesced per row)
    if (side) {
        #pragma unroll
        for (int j = 0; j < NPB; j++)
            g_hr[(n0 + j) * UNITS + col] = h[j];
    }

    // per-node attention scalars: al (side 0) / ar (side 1)
    const float wa = W_attn[side * UNITS + col];
    __shared__ float s_red[2][NPB][4];
    const int wloc = (t >> 5) & 3, lane = t & 31;

    #pragma unroll
    for (int j = 0; j < NPB; j++) {
        float p = lrelu(h[j]) * wa;
        #pragma unroll
        for (int o = 16; o > 0; o >>= 1)
            p += __shfl_down_sync(0xffffffffu, p, o);
        if (lane == 0) s_red[side][j][wloc] = p;
    }
    __syncthreads();
    if (t < NPB) {
        g_al[n0 + t] = s_red[0][t][0] + s_red[0][t][1] + s_red[0][t][2] + s_red[0][t][3];
    } else if (t < 2 * NPB) {
        const int j = t - NPB;
        g_ar[n0 + j] = s_red[1][j][0] + s_red[1][j][1] + s_red[1][j][2] + s_red[1][j][3];
    }
}

// Kernel 2: 2 nodes per block, 256 threads (8 warps -> ~86% occ).
// Phase A (t<128): one edge score per thread (src == n exploited).
// Phase B (all 8 warps): warp w aggregates 16 edges of node (w>>2)
//         with 2 independent float4 chains, L2-streaming loads.
__global__ __launch_bounds__(256)
void attn_kernel(const int* __restrict__ edges,
                 const float* __restrict__ ef,
                 const float* __restrict__ W_edge,
                 const float* __restrict__ W_attn,
                 float* __restrict__ out) {
    const int n0 = blockIdx.x * 2;
    const int t  = threadIdx.x;
    const int w = t >> 5, lane = t & 31;

    __shared__ float s_wev[FE_DIM];
    __shared__ float s_score[2 * DEG];
    __shared__ int   s_dst[2 * DEG];
    __shared__ float s_acc[8][UNITS];
    __shared__ float s_part[4];
    __shared__ float s_inv[2];

    if (t < 2 * DEG)
        s_dst[t] = reinterpret_cast<const int2*>(edges)[n0 * DEG + t].y;

    if (t < FE_DIM) {
        float s = 0.0f;
        #pragma unroll
        for (int j = 0; j < FE_DIM; j++)
            s += W_edge[t * FE_DIM + j] * W_attn[2 * UNITS + j];
        s_wev[t] = s;
    }
    __syncthreads();

    if (t < 2 * DEG) {
        const int n   = n0 + (t >> 6);
        const int dst = s_dst[t];
        const float4* p = reinterpret_cast<const float4*>(
            ef + ((size_t)n * N_NODES + (size_t)dst) * FE_DIM);
        float dot = 0.0f;
        #pragma unroll
        for (int i = 0; i < 4; i++) {
            const float4 v = __ldcs(p + i);   // zero-reuse stream
            dot = fmaf(v.x, s_wev[4 * i + 0], dot);
            dot = fmaf(v.y, s_wev[4 * i + 1], dot);
            dot = fmaf(v.z, s_wev[4 * i + 2], dot);
            dot = fmaf(v.w, s_wev[4 * i + 3], dot);
        }
        float s = g_al[n] + g_ar[dst] + dot;
        s = fminf(2.0f, fmaxf(-2.0f, s));
        const float sc = __expf(s);
        s_score[t] = sc;

        float v = sc;
        #pragma unroll
        for (int o = 16; o > 0; o >>= 1)
            v += __shfl_down_sync(0xffffffffu, v, o);
        if (lane == 0) s_part[w] = v;
    }
    __syncthreads();
    if (t < 2) s_inv[t] = 1.0f / (s_part[2 * t] + s_part[2 * t + 1]);

    // warp w: node (w>>2), edges [(w&3)*16, +16) of that node's 64
    const int ebase = (w >> 2) * DEG + (w & 3) * 16;
    float4 a0 = make_float4(0.f, 0.f, 0.f, 0.f);
    float4 a1 = make_float4(0.f, 0.f, 0.f, 0.f);
    #pragma unroll
    for (int i = 0; i < 8; i++) {
        const int e0 = ebase + i;
        const int e1 = ebase + 8 + i;
        const float sc0 = s_score[e0];
        const float sc1 = s_score[e1];
        const float4 h0 = __ldcg(reinterpret_cast<const float4*>(
            g_hr + s_dst[e0] * UNITS + lane * 4));
        const float4 h1 = __ldcg(reinterpret_cast<const float4*>(
            g_hr + s_dst[e1] * UNITS + lane * 4));
        a0.x = fmaf(sc0, h0.x, a0.x);  a1.x = fmaf(sc1, h1.x, a1.x);
        a0.y = fmaf(sc0, h0.y, a0.y);  a1.y = fmaf(sc1, h1.y, a1.y);
        a0.z = fmaf(sc0, h0.z, a0.z);  a1.z = fmaf(sc1, h1.z, a1.z);
        a0.w = fmaf(sc0, h0.w, a0.w);  a1.w = fmaf(sc1, h1.w, a1.w);
    }
    a0.x += a1.x; a0.y += a1.y; a0.z += a1.z; a0.w += a1.w;
    *reinterpret_cast<float4*>(&s_acc[w][lane * 4]) = a0;
    __syncthreads();

    // 256 outputs: node j = t>>7, column t&127
    const int j = t >> 7, col = t & 127;
    const float val = s_acc[4 * j + 0][col] + s_acc[4 * j + 1][col]
                    + s_acc[4 * j + 2][col] + s_acc[4 * j + 3][col];
    out[(n0 + j) * UNITS + col] = val * s_inv[j];
}

extern "C" void kernel_launch(void* const* d_in, const int* in_sizes, int n_in,
                              void* d_out, int out_size) {
    const float* ns      = (const float*)d_in[0];
    const int*   edges   = (const int*)d_in[1];
    const float* ef      = (const float*)d_in[2];
    const float* W_left  = (const float*)d_in[3];
    const float* W_right = (const float*)d_in[4];
    const float* W_attn  = (const float*)d_in[5];
    const float* W_edge  = (const float*)d_in[6];
    float* out = (float*)d_out;

    gemm_kernel<<<N_NODES / NPB, 256>>>(ns, W_left, W_right, W_attn);
    attn_kernel<<<N_NODES / 2, 256>>>(edges, ef, W_edge, W_attn, out);
}

// round 5
// speedup vs baseline: 1.2061x; 1.2061x over previous
#include <cuda_runtime.h>
#include <cstdint>

#define N_NODES 2048
#define F_DIM   128
#define UNITS   128
#define FE_DIM  16
#define DEG     64

#define GRID        1024
#define GEMM_BLOCKS 256
#define NPB         8      // gemm nodes per gemm-block
#define NSPAD       12     // smem row pad (float4-aligned)

__device__ float g_hr[N_NODES * UNITS];
__device__ float g_al[N_NODES];
__device__ float g_ar[N_NODES];
__device__ unsigned g_bar = 0;   // monotonic grid barrier counter

__device__ __forceinline__ float lrelu(float x) {
    return x > 0.0f ? x : 0.2f * x;
}

__global__ __launch_bounds__(128, 8)
void fused_kernel(const float* __restrict__ ns,
                  const int* __restrict__ edges,
                  const float* __restrict__ ef,
                  const float* __restrict__ Wl,
                  const float* __restrict__ Wr,
                  const float* __restrict__ W_attn,
                  const float* __restrict__ W_edge,
                  float* __restrict__ out) {
    const int b = blockIdx.x;
    const int t = threadIdx.x;
    const int w = t >> 5, lane = t & 31;

    __shared__ float s_ns[F_DIM][NSPAD];      // gemm node tile (gemm blocks only)
    __shared__ float s_redL[NPB][4];
    __shared__ float s_redR[NPB][4];
    __shared__ float s_wev[FE_DIM];
    __shared__ float s_score[2 * DEG];
    __shared__ int   s_dst[2 * DEG];
    __shared__ float s_acc[4][UNITS];
    __shared__ float s_part[4];
    __shared__ float s_inv[2];
    __shared__ unsigned s_ticket;

    // ---------------- Phase 1: GEMM (blocks 0..255) ----------------
    if (b < GEMM_BLOCKS) {
        const int n0 = b * NPB;
        #pragma unroll
        for (int j = 0; j < NPB; j++)
            s_ns[t][j] = ns[(n0 + j) * F_DIM + t];
        __syncthreads();

        float accL[NPB], accR[NPB];
        #pragma unroll
        for (int j = 0; j < NPB; j++) { accL[j] = 0.0f; accR[j] = 0.0f; }

        #pragma unroll 8
        for (int k = 0; k < F_DIM; k++) {
            const float wl = Wl[k * UNITS + t];
            const float wr = Wr[k * UNITS + t];
            const float4 a0 = *reinterpret_cast<const float4*>(&s_ns[k][0]);
            const float4 a1 = *reinterpret_cast<const float4*>(&s_ns[k][4]);
            accL[0] = fmaf(a0.x, wl, accL[0]);  accR[0] = fmaf(a0.x, wr, accR[0]);
            accL[1] = fmaf(a0.y, wl, accL[1]);  accR[1] = fmaf(a0.y, wr, accR[1]);
            accL[2] = fmaf(a0.z, wl, accL[2]);  accR[2] = fmaf(a0.z, wr, accR[2]);
            accL[3] = fmaf(a0.w, wl, accL[3]);  accR[3] = fmaf(a0.w, wr, accR[3]);
            accL[4] = fmaf(a1.x, wl, accL[4]);  accR[4] = fmaf(a1.x, wr, accR[4]);
            accL[5] = fmaf(a1.y, wl, accL[5]);  accR[5] = fmaf(a1.y, wr, accR[5]);
            accL[6] = fmaf(a1.z, wl, accL[6]);  accR[6] = fmaf(a1.z, wr, accR[6]);
            accL[7] = fmaf(a1.w, wl, accL[7]);  accR[7] = fmaf(a1.w, wr, accR[7]);
        }

        #pragma unroll
        for (int j = 0; j < NPB; j++)
            g_hr[(n0 + j) * UNITS + t] = accR[j];

        const float wa_l = W_attn[t];
        const float wa_r = W_attn[UNITS + t];
        #pragma unroll
        for (int j = 0; j < NPB; j++) {
            float pl = lrelu(accL[j]) * wa_l;
            float pr = lrelu(accR[j]) * wa_r;
            #pragma unroll
            for (int o = 16; o > 0; o >>= 1) {
                pl += __shfl_down_sync(0xffffffffu, pl, o);
                pr += __shfl_down_sync(0xffffffffu, pr, o);
            }
            if (lane == 0) { s_redL[j][w] = pl; s_redR[j][w] = pr; }
        }
        __syncthreads();
        if (t < NPB) {
            g_al[n0 + t] = s_redL[t][0] + s_redL[t][1] + s_redL[t][2] + s_redL[t][3];
        } else if (t < 2 * NPB) {
            const int j = t - NPB;
            g_ar[n0 + j] = s_redR[j][0] + s_redR[j][1] + s_redR[j][2] + s_redR[j][3];
        }
        __syncthreads();   // all gemm stores issued before arrive
    }

    // ---------------- Barrier arrive (release) ----------------
    if (t == 0) {
        __threadfence();
        s_ticket = atomicAdd(&g_bar, 1u);
    }

    // ---------------- Phase 2a: pre-barrier attn work (overlaps gemm) ----
    const int n0a = b * 2;                 // this block's two attn nodes
    const int n   = n0a + (t >> 6);        // node of this thread's edge

    s_dst[t] = reinterpret_cast<const int2*>(edges)[n0a * DEG + t].y;

    if (t < FE_DIM) {
        float s = 0.0f;
        #pragma unroll
        for (int j = 0; j < FE_DIM; j++)
            s += W_edge[t * FE_DIM + j] * W_attn[2 * UNITS + j];
        s_wev[t] = s;
    }
    __syncthreads();

    const int dst = s_dst[t];
    const float4* p = reinterpret_cast<const float4*>(
        ef + ((size_t)n * N_NODES + (size_t)dst) * FE_DIM);
    float dot = 0.0f;
    #pragma unroll
    for (int i = 0; i < 4; i++) {
        const float4 v = p[i];
        dot = fmaf(v.x, s_wev[4 * i + 0], dot);
        dot = fmaf(v.y, s_wev[4 * i + 1], dot);
        dot = fmaf(v.z, s_wev[4 * i + 2], dot);
        dot = fmaf(v.w, s_wev[4 * i + 3], dot);
    }

    // ---------------- Barrier wait (acquire) ----------------
    if (t == 0) {
        const unsigned target = (s_ticket & ~(unsigned)(GRID - 1)) + GRID;
        while ((int)(*(volatile unsigned*)&g_bar - target) < 0)
            __nanosleep(64);
        __threadfence();
    }
    __syncthreads();

    // ---------------- Phase 2b: scores + softmax ----------------
    float s = g_al[n] + g_ar[dst] + dot;
    s = fminf(2.0f, fmaxf(-2.0f, s));
    const float sc = __expf(s);
    s_score[t] = sc;

    float v = sc;
    #pragma unroll
    for (int o = 16; o > 0; o >>= 1)
        v += __shfl_down_sync(0xffffffffu, v, o);
    if (lane == 0) s_part[w] = v;
    __syncthreads();
    if (t < 2) s_inv[t] = 1.0f / (s_part[2 * t] + s_part[2 * t + 1]);

    // ---------------- Phase 2c: weighted aggregation ----------------
    // warp w -> node (w>>1), edges [(w&1)*32, +32); two independent chains.
    const int ebase = (w >> 1) * DEG + (w & 1) * 32;
    float4 a0 = make_float4(0.f, 0.f, 0.f, 0.f);
    float4 a1 = make_float4(0.f, 0.f, 0.f, 0.f);
    #pragma unroll
    for (int i = 0; i < 16; i++) {
        const int e0 = ebase + i;
        const int e1 = ebase + 16 + i;
        const float sc0 = s_score[e0];
        const float sc1 = s_score[e1];
        const float4 h0 = *reinterpret_cast<const float4*>(
            g_hr + s_dst[e0] * UNITS + lane * 4);
        const float4 h1 = *reinterpret_cast<const float4*>(
            g_hr + s_dst[e1] * UNITS + lane * 4);
        a0.x = fmaf(sc0, h0.x, a0.x);  a1.x = fmaf(sc1, h1.x, a1.x);
        a0.y = fmaf(sc0, h0.y, a0.y);  a1.y = fmaf(sc1, h1.y, a1.y);
        a0.z = fmaf(sc0, h0.z, a0.z);  a1.z = fmaf(sc1, h1.z, a1.z);
        a0.w = fmaf(sc0, h0.w, a0.w);  a1.w = fmaf(sc1, h1.w, a1.w);
    }
    a0.x += a1.x; a0.y += a1.y; a0.z += a1.z; a0.w += a1.w;
    *reinterpret_cast<float4*>(&s_acc[w][lane * 4]) = a0;
    __syncthreads();

    // thread t writes column t of both nodes
    out[n0a * UNITS + t]       = (s_acc[0][t] + s_acc[1][t]) * s_inv[0];
    out[(n0a + 1) * UNITS + t] = (s_acc[2][t] + s_acc[3][t]) * s_inv[1];
}

extern "C" void kernel_launch(void* const* d_in, const int* in_sizes, int n_in,
                              void* d_out, int out_size) {
    const float* ns      = (const float*)d_in[0];
    const int*   edges   = (const int*)d_in[1];
    const float* ef      = (const float*)d_in[2];
    const float* W_left  = (const float*)d_in[3];
    const float* W_right = (const float*)d_in[4];
    const float* W_attn  = (const float*)d_in[5];
    const float* W_edge  = (const float*)d_in[6];
    float* out = (float*)d_out;

    fused_kernel<<<GRID, 128>>>(ns, edges, ef, W_left, W_right,
                                W_attn, W_edge, out);
}